// round 1
// baseline (speedup 1.0000x reference)
#include <cuda_runtime.h>
#include <cuda_bf16.h>

#define N_NODES 100000
#define N_EDGES 1000000
#define DF 64
#define NC 16

// ---------------- device scratch (no allocations allowed) ----------------
__device__ float g_deg[N_NODES];
__device__ float g_dinv[N_NODES];
__device__ float g_h1[(size_t)N_NODES * DF];    // X @ W1
__device__ float g_agg1[(size_t)N_NODES * DF];  // aggregated layer1 -> relu'd x1
__device__ float g_h2[(size_t)N_NODES * NC];    // x1 @ W2
__device__ int   g_idx64;                       // 1 if edge_idx stored as int64

// ---------------- edge index access (int32 or int64 storage) -------------
__device__ __forceinline__ int edge_at(const void* edges, long long pos) {
    if (g_idx64)
        return (int)((const long long*)edges)[pos];
    return ((const int*)edges)[pos];
}

// Detect whether edge buffer is int64 (little-endian high words all zero)
__global__ void detect_idx_kernel(const int* e32) {
    __shared__ int any_nonzero;
    if (threadIdx.x == 0) any_nonzero = 0;
    __syncthreads();
    // check high words of the first 4096 "int64" values
    for (int i = threadIdx.x; i < 4096; i += blockDim.x) {
        if (e32[2 * i + 1] != 0) any_nonzero = 1;
    }
    __syncthreads();
    if (threadIdx.x == 0) g_idx64 = (any_nonzero == 0) ? 1 : 0;
}

// ---------------- zero scratch + output ----------------------------------
__global__ void zero_kernel(float* __restrict__ dout) {
    long long i = (long long)blockIdx.x * blockDim.x + threadIdx.x;
    if (i < (long long)N_NODES * DF) g_agg1[i] = 0.0f;
    if (i < N_NODES)                 g_deg[i] = 0.0f;
    if (i < (long long)N_NODES * NC) dout[i] = 0.0f;
}

// ---------------- degree (in-degree over dst) -----------------------------
__global__ void degree_kernel(const void* __restrict__ edges) {
    int e = blockIdx.x * blockDim.x + threadIdx.x;
    if (e < N_EDGES) {
        int d = edge_at(edges, (long long)N_EDGES + e);
        atomicAdd(&g_deg[d], 1.0f);
    }
}

__global__ void dinv_kernel() {
    int i = blockIdx.x * blockDim.x + threadIdx.x;
    if (i < N_NODES) {
        // self-loop contributes +1; deg+1 > 0 always
        g_dinv[i] = rsqrtf(g_deg[i] + 1.0f);
    }
}

// ---------------- GEMM1: h1 = X @ W1  (100k x 64 @ 64 x 64) ---------------
__global__ void gemm1_kernel(const float* __restrict__ X,
                             const float* __restrict__ W1) {
    __shared__ float Ws[64 * 64];
    int tid = threadIdx.y * 64 + threadIdx.x;
    for (int i = tid; i < 64 * 64; i += 256) Ws[i] = W1[i];
    __syncthreads();

    int node = blockIdx.x * 4 + threadIdx.y;
    if (node >= N_NODES) return;
    const float* x = X + (size_t)node * DF;
    int c = threadIdx.x;
    float acc = 0.0f;
#pragma unroll
    for (int k = 0; k < 64; k++) acc = fmaf(__ldg(&x[k]), Ws[k * 64 + c], acc);
    g_h1[(size_t)node * DF + c] = acc;
}

// ---------------- scatter layer 1: agg1[dst] += h1[src]*norm --------------
// 16 threads per edge, each does one red.global.add.v4.f32 (4 floats)
__global__ void scatter1_kernel(const void* __restrict__ edges) {
    long long gid = (long long)blockIdx.x * blockDim.x + threadIdx.x;
    long long e = gid >> 4;
    int part = (int)(gid & 15);
    if (e >= N_EDGES) return;
    int s = edge_at(edges, e);
    int d = edge_at(edges, (long long)N_EDGES + e);
    float nrm = g_dinv[s] * g_dinv[d];
    float4 v = ((const float4*)(g_h1 + (size_t)s * DF))[part];
    float* dstp = g_agg1 + (size_t)d * DF + part * 4;
    asm volatile("red.global.add.v4.f32 [%0], {%1, %2, %3, %4};"
                 :: "l"(dstp), "f"(v.x * nrm), "f"(v.y * nrm),
                    "f"(v.z * nrm), "f"(v.w * nrm)
                 : "memory");
}

// ---------------- self-loop + bias + relu ---------------------------------
__global__ void post1_kernel(const float* __restrict__ b1) {
    long long i = (long long)blockIdx.x * blockDim.x + threadIdx.x;
    if (i >= (long long)N_NODES * DF) return;
    int node = (int)(i >> 6);
    int c = (int)(i & 63);
    float di = g_dinv[node];
    float v = g_agg1[i] + g_h1[i] * di * di + b1[c];
    g_agg1[i] = fmaxf(v, 0.0f);
}

// ---------------- GEMM2: h2 = x1 @ W2  (100k x 64 @ 64 x 16) --------------
__global__ void gemm2_kernel(const float* __restrict__ W2) {
    __shared__ float Ws[64 * 16];
    int tid = threadIdx.y * 16 + threadIdx.x;
    for (int i = tid; i < 64 * 16; i += 256) Ws[i] = W2[i];
    __syncthreads();

    int node = blockIdx.x * 16 + threadIdx.y;
    if (node >= N_NODES) return;
    const float* x = g_agg1 + (size_t)node * DF;
    int c = threadIdx.x;
    float acc = 0.0f;
#pragma unroll
    for (int k = 0; k < 64; k++) acc = fmaf(x[k], Ws[k * 16 + c], acc);
    g_h2[(size_t)node * NC + c] = acc;
}

// ---------------- scatter layer 2: out[dst] += h2[src]*norm ---------------
// 4 threads per edge, each does one red.global.add.v4.f32
__global__ void scatter2_kernel(const void* __restrict__ edges,
                                float* __restrict__ dout) {
    long long gid = (long long)blockIdx.x * blockDim.x + threadIdx.x;
    long long e = gid >> 2;
    int part = (int)(gid & 3);
    if (e >= N_EDGES) return;
    int s = edge_at(edges, e);
    int d = edge_at(edges, (long long)N_EDGES + e);
    float nrm = g_dinv[s] * g_dinv[d];
    float4 v = ((const float4*)(g_h2 + (size_t)s * NC))[part];
    float* dstp = dout + (size_t)d * NC + part * 4;
    asm volatile("red.global.add.v4.f32 [%0], {%1, %2, %3, %4};"
                 :: "l"(dstp), "f"(v.x * nrm), "f"(v.y * nrm),
                    "f"(v.z * nrm), "f"(v.w * nrm)
                 : "memory");
}

// ---------------- finalize: self-loop + bias ------------------------------
__global__ void final2_kernel(const float* __restrict__ b2,
                              float* __restrict__ dout) {
    long long i = (long long)blockIdx.x * blockDim.x + threadIdx.x;
    if (i >= (long long)N_NODES * NC) return;
    int node = (int)(i >> 4);
    int c = (int)(i & 15);
    float di = g_dinv[node];
    dout[i] += g_h2[i] * di * di + b2[c];
}

// ---------------- launch --------------------------------------------------
extern "C" void kernel_launch(void* const* d_in, const int* in_sizes, int n_in,
                              void* d_out, int out_size) {
    const float* X  = (const float*)d_in[0];
    const void*  EI = (const void*)d_in[1];
    const float* W1 = (const float*)d_in[2];
    const float* b1 = (const float*)d_in[3];
    const float* W2 = (const float*)d_in[4];
    const float* b2 = (const float*)d_in[5];
    float* dout = (float*)d_out;

    (void)in_sizes; (void)n_in; (void)out_size;

    const int T = 256;

    // zero scratch + output
    zero_kernel<<<(N_NODES * DF + T - 1) / T, T>>>(dout);
    // detect int32 vs int64 edge storage
    detect_idx_kernel<<<1, 256>>>((const int*)EI);
    // degrees + dinv
    degree_kernel<<<(N_EDGES + T - 1) / T, T>>>(EI);
    dinv_kernel<<<(N_NODES + T - 1) / T, T>>>();
    // layer 1
    gemm1_kernel<<<(N_NODES + 3) / 4, dim3(64, 4)>>>(X, W1);
    scatter1_kernel<<<(int)(((long long)N_EDGES * 16 + T - 1) / T), T>>>(EI);
    post1_kernel<<<(int)(((long long)N_NODES * DF + T - 1) / T), T>>>(b1);
    // layer 2
    gemm2_kernel<<<(N_NODES + 15) / 16, dim3(16, 16)>>>(W2);
    scatter2_kernel<<<(int)(((long long)N_EDGES * 4 + T - 1) / T), T>>>(EI, dout);
    final2_kernel<<<(int)(((long long)N_NODES * NC + T - 1) / T), T>>>(b2, dout);
}

// round 2
// speedup vs baseline: 1.6721x; 1.6721x over previous
#include <cuda_runtime.h>
#include <cuda_bf16.h>

#define N_NODES 100000
#define N_EDGES 1000000
#define DF 64
#define NC 16
#define SCAN_BLK 1024
#define NB ((N_NODES + SCAN_BLK - 1) / SCAN_BLK)   // 98

// ---------------- device scratch (no allocations allowed) ----------------
__device__ int   g_degi[N_NODES];
__device__ float g_dinv[N_NODES];
__device__ int   g_off[N_NODES + 1];
__device__ int   g_cur[N_NODES];
__device__ int   g_bsum[NB];
__device__ int   g_boff[NB];
__device__ int   g_srcs[N_EDGES];
__device__ float g_nrm[N_EDGES];                 // dinv[src] per sorted edge
__device__ float g_h1[(size_t)N_NODES * DF];     // X @ W1
__device__ float g_x1[(size_t)N_NODES * DF];     // relu(A_hat h1 + b1)
__device__ float g_h2[(size_t)N_NODES * NC];     // x1 @ W2
__device__ int   g_idx64;

// ---------------- edge index access (int32 or int64 storage) -------------
__device__ __forceinline__ int edge_at(const void* edges, long long pos) {
    if (g_idx64)
        return (int)((const long long*)edges)[pos];
    return ((const int*)edges)[pos];
}

__global__ void detect_idx_kernel(const int* e32) {
    __shared__ int any_nonzero;
    if (threadIdx.x == 0) any_nonzero = 0;
    __syncthreads();
    for (int i = threadIdx.x; i < 4096; i += blockDim.x)
        if (e32[2 * i + 1] != 0) any_nonzero = 1;
    __syncthreads();
    if (threadIdx.x == 0) g_idx64 = (any_nonzero == 0) ? 1 : 0;
}

// ---------------- init + degree -------------------------------------------
__global__ void init_kernel() {
    int i = blockIdx.x * blockDim.x + threadIdx.x;
    if (i < N_NODES) g_degi[i] = 0;
}

__global__ void degree_kernel(const void* __restrict__ edges) {
    int e = blockIdx.x * blockDim.x + threadIdx.x;
    if (e < N_EDGES) {
        int d = edge_at(edges, (long long)N_EDGES + e);
        atomicAdd(&g_degi[d], 1);
    }
}

__global__ void dinv_kernel() {
    int i = blockIdx.x * blockDim.x + threadIdx.x;
    if (i < N_NODES) g_dinv[i] = rsqrtf((float)g_degi[i] + 1.0f);
}

// ---------------- prefix scan (3-phase) -----------------------------------
__global__ void scan_p1() {   // block partial sums
    __shared__ int sdata[SCAN_BLK];
    int i = blockIdx.x * SCAN_BLK + threadIdx.x;
    sdata[threadIdx.x] = (i < N_NODES) ? g_degi[i] : 0;
    __syncthreads();
    for (int s = SCAN_BLK / 2; s > 0; s >>= 1) {
        if (threadIdx.x < s) sdata[threadIdx.x] += sdata[threadIdx.x + s];
        __syncthreads();
    }
    if (threadIdx.x == 0) g_bsum[blockIdx.x] = sdata[0];
}

__global__ void scan_p2() {   // exclusive scan of NB partials (serial, tiny)
    if (threadIdx.x == 0) {
        int acc = 0;
        for (int i = 0; i < NB; i++) { g_boff[i] = acc; acc += g_bsum[i]; }
    }
}

__global__ void scan_p3() {   // per-block exclusive scan -> offsets + cursors
    __shared__ int wsum[32];
    int t = threadIdx.x;
    int i = blockIdx.x * SCAN_BLK + t;
    int v = (i < N_NODES) ? g_degi[i] : 0;
    int lane = t & 31, w = t >> 5;
    int x = v;
#pragma unroll
    for (int off = 1; off < 32; off <<= 1) {
        int y = __shfl_up_sync(0xffffffffu, x, off);
        if (lane >= off) x += y;
    }
    if (lane == 31) wsum[w] = x;
    __syncthreads();
    if (w == 0) {
        int y = wsum[lane];
#pragma unroll
        for (int off = 1; off < 32; off <<= 1) {
            int z = __shfl_up_sync(0xffffffffu, y, off);
            if (lane >= off) y += z;
        }
        wsum[lane] = y;
    }
    __syncthreads();
    int incl = x + ((w > 0) ? wsum[w - 1] : 0) + g_boff[blockIdx.x];
    if (i < N_NODES) {
        g_off[i] = incl - v;
        g_cur[i] = incl - v;
        if (i == N_NODES - 1) g_off[N_NODES] = incl;
    }
}

// ---------------- CSR build (counting-sort scatter) -----------------------
__global__ void build_csr(const void* __restrict__ edges) {
    int e = blockIdx.x * blockDim.x + threadIdx.x;
    if (e >= N_EDGES) return;
    int s = edge_at(edges, e);
    int d = edge_at(edges, (long long)N_EDGES + e);
    int pos = atomicAdd(&g_cur[d], 1);
    g_srcs[pos] = s;
    g_nrm[pos]  = g_dinv[s];
}

// ---------------- GEMM1: h1 = X @ W1 (64 nodes/block, 4x4 blocked) --------
__global__ __launch_bounds__(256) void gemm1_kernel(const float* __restrict__ X,
                                                    const float* __restrict__ W1) {
    __shared__ float xs[64 * 65];
    __shared__ float ws[64 * 64];
    int tid = threadIdx.x;
    int base = blockIdx.x * 64;
    for (int i = tid; i < 64 * 64; i += 256) ws[i] = W1[i];
    for (int i = tid; i < 64 * 64; i += 256) {
        int n = i >> 6, k = i & 63;
        int node = base + n;
        xs[n * 65 + k] = (node < N_NODES) ? X[(size_t)node * 64 + k] : 0.0f;
    }
    __syncthreads();

    int node_t = tid >> 4;   // 0..15
    int col_t  = tid & 15;   // 0..15
    float acc[4][4] = {};
#pragma unroll
    for (int k = 0; k < 64; k++) {
        float xv[4], wv[4];
#pragma unroll
        for (int i = 0; i < 4; i++) xv[i] = xs[(node_t * 4 + i) * 65 + k];
#pragma unroll
        for (int j = 0; j < 4; j++) wv[j] = ws[k * 64 + col_t + 16 * j];
#pragma unroll
        for (int i = 0; i < 4; i++)
#pragma unroll
            for (int j = 0; j < 4; j++) acc[i][j] = fmaf(xv[i], wv[j], acc[i][j]);
    }
#pragma unroll
    for (int i = 0; i < 4; i++) {
        int node = base + node_t * 4 + i;
        if (node < N_NODES) {
#pragma unroll
            for (int j = 0; j < 4; j++)
                g_h1[(size_t)node * 64 + col_t + 16 * j] = acc[i][j];
        }
    }
}

// ---------------- agg1: x1 = relu(A_hat h1 + b1) (gather, no atomics) -----
__global__ __launch_bounds__(256) void agg1_kernel(const float* __restrict__ b1) {
    int node = blockIdx.x * 4 + threadIdx.y;
    if (node >= N_NODES) return;
    int c = threadIdx.x;
    int beg = g_off[node], end = g_off[node + 1];
    float di = g_dinv[node];
    float acc = g_h1[(size_t)node * 64 + c] * di;   // self loop (x di later)
    int i = beg;
    for (; i + 1 < end; i += 2) {
        int s0 = g_srcs[i], s1 = g_srcs[i + 1];
        float w0 = g_nrm[i], w1 = g_nrm[i + 1];
        float v0 = __ldg(&g_h1[(size_t)s0 * 64 + c]);
        float v1 = __ldg(&g_h1[(size_t)s1 * 64 + c]);
        acc = fmaf(v0, w0, acc);
        acc = fmaf(v1, w1, acc);
    }
    if (i < end) {
        int s = g_srcs[i];
        acc = fmaf(__ldg(&g_h1[(size_t)s * 64 + c]), g_nrm[i], acc);
    }
    float r = fmaf(acc, di, b1[c]);
    g_x1[(size_t)node * 64 + c] = fmaxf(r, 0.0f);
}

// ---------------- GEMM2: h2 = x1 @ W2 (128 nodes/block, 2x4 blocked) ------
__global__ __launch_bounds__(256) void gemm2_kernel(const float* __restrict__ W2) {
    __shared__ float xs[128 * 65];
    __shared__ float ws[64 * 16];
    int tid = threadIdx.x;
    int base = blockIdx.x * 128;
    for (int i = tid; i < 64 * 16; i += 256) ws[i] = W2[i];
    for (int i = tid; i < 128 * 64; i += 256) {
        int n = i >> 6, k = i & 63;
        int node = base + n;
        xs[n * 65 + k] = (node < N_NODES) ? g_x1[(size_t)node * 64 + k] : 0.0f;
    }
    __syncthreads();

    int node_t = tid >> 2;   // 0..63
    int col_t  = tid & 3;    // 0..3
    float acc[2][4] = {};
#pragma unroll
    for (int k = 0; k < 64; k++) {
        float xv[2], wv[4];
#pragma unroll
        for (int i = 0; i < 2; i++) xv[i] = xs[(node_t * 2 + i) * 65 + k];
#pragma unroll
        for (int j = 0; j < 4; j++) wv[j] = ws[k * 16 + col_t + 4 * j];
#pragma unroll
        for (int i = 0; i < 2; i++)
#pragma unroll
            for (int j = 0; j < 4; j++) acc[i][j] = fmaf(xv[i], wv[j], acc[i][j]);
    }
#pragma unroll
    for (int i = 0; i < 2; i++) {
        int node = base + node_t * 2 + i;
        if (node < N_NODES) {
#pragma unroll
            for (int j = 0; j < 4; j++)
                g_h2[(size_t)node * 16 + col_t + 4 * j] = acc[i][j];
        }
    }
}

// ---------------- agg2: out = A_hat h2 + b2 (gather, fused finalize) ------
__global__ __launch_bounds__(256) void agg2_kernel(const float* __restrict__ b2,
                                                   float* __restrict__ dout) {
    int node = blockIdx.x * 16 + threadIdx.y;
    if (node >= N_NODES) return;
    int c = threadIdx.x;
    int beg = g_off[node], end = g_off[node + 1];
    float di = g_dinv[node];
    float acc = g_h2[(size_t)node * 16 + c] * di;
    int i = beg;
    for (; i + 1 < end; i += 2) {
        int s0 = g_srcs[i], s1 = g_srcs[i + 1];
        float w0 = g_nrm[i], w1 = g_nrm[i + 1];
        float v0 = __ldg(&g_h2[(size_t)s0 * 16 + c]);
        float v1 = __ldg(&g_h2[(size_t)s1 * 16 + c]);
        acc = fmaf(v0, w0, acc);
        acc = fmaf(v1, w1, acc);
    }
    if (i < end) {
        int s = g_srcs[i];
        acc = fmaf(__ldg(&g_h2[(size_t)s * 16 + c]), g_nrm[i], acc);
    }
    dout[(size_t)node * 16 + c] = fmaf(acc, di, b2[c]);
}

// ---------------- launch --------------------------------------------------
extern "C" void kernel_launch(void* const* d_in, const int* in_sizes, int n_in,
                              void* d_out, int out_size) {
    const float* X  = (const float*)d_in[0];
    const void*  EI = (const void*)d_in[1];
    const float* W1 = (const float*)d_in[2];
    const float* b1 = (const float*)d_in[3];
    const float* W2 = (const float*)d_in[4];
    const float* b2 = (const float*)d_in[5];
    float* dout = (float*)d_out;
    (void)in_sizes; (void)n_in; (void)out_size;

    const int T = 256;

    detect_idx_kernel<<<1, 256>>>((const int*)EI);
    init_kernel<<<(N_NODES + T - 1) / T, T>>>();
    degree_kernel<<<(N_EDGES + T - 1) / T, T>>>(EI);
    dinv_kernel<<<(N_NODES + T - 1) / T, T>>>();
    scan_p1<<<NB, SCAN_BLK>>>();
    scan_p2<<<1, 32>>>();
    scan_p3<<<NB, SCAN_BLK>>>();
    build_csr<<<(N_EDGES + T - 1) / T, T>>>(EI);

    gemm1_kernel<<<(N_NODES + 63) / 64, 256>>>(X, W1);
    agg1_kernel<<<(N_NODES + 3) / 4, dim3(64, 4)>>>(b1);
    gemm2_kernel<<<(N_NODES + 127) / 128, 256>>>(W2);
    agg2_kernel<<<(N_NODES + 15) / 16, dim3(16, 16)>>>(b2, dout);
}

// round 4
// speedup vs baseline: 1.7741x; 1.0610x over previous
#include <cuda_runtime.h>
#include <cuda_bf16.h>

#define N_NODES 100000
#define N_EDGES 1000000
#define DF 64
#define NC 16
#define SCAN_BLK 1024
#define NB ((N_NODES + SCAN_BLK - 1) / SCAN_BLK)   // 98

// ---------------- device scratch (no allocations allowed) ----------------
__device__ int   g_degi[N_NODES];
__device__ float g_dinv[N_NODES];
__device__ int   g_off[N_NODES + 1];
__device__ int   g_cur[N_NODES];
__device__ int   g_bsum[NB];
__device__ int2  g_edge[N_EDGES];                // packed (src, bits(dinv[src]))
__device__ float g_h1[(size_t)N_NODES * DF];     // X @ W1
__device__ float g_x1[(size_t)N_NODES * DF];     // relu(A_hat h1 + b1)
__device__ float g_h2[(size_t)N_NODES * NC];     // x1 @ W2
__device__ int   g_idx64;

// ---------------- edge index access (int32 or int64 storage) -------------
__device__ __forceinline__ int edge_at(const void* edges, long long pos) {
    if (g_idx64)
        return (int)((const long long*)edges)[pos];
    return ((const int*)edges)[pos];
}

// ---------------- pre: zero degrees + detect index width ------------------
__global__ void pre_kernel(const int* __restrict__ e32) {
    int i = blockIdx.x * blockDim.x + threadIdx.x;
    if (i < N_NODES) g_degi[i] = 0;
    if (blockIdx.x == 0) {
        __shared__ int any_nonzero;
        if (threadIdx.x == 0) any_nonzero = 0;
        __syncthreads();
        for (int j = threadIdx.x; j < 4096; j += blockDim.x)
            if (e32[2 * j + 1] != 0) any_nonzero = 1;
        __syncthreads();
        if (threadIdx.x == 0) g_idx64 = (any_nonzero == 0) ? 1 : 0;
    }
}

// ---------------- degree (in-degree over dst) ------------------------------
__global__ void degree_kernel(const void* __restrict__ edges) {
    int e = blockIdx.x * blockDim.x + threadIdx.x;
    if (e < N_EDGES) {
        int d = edge_at(edges, (long long)N_EDGES + e);
        atomicAdd(&g_degi[d], 1);
    }
}

// ---------------- scan phase 1: block sums + dinv --------------------------
__global__ void scan_p1() {
    __shared__ int sdata[SCAN_BLK];
    int i = blockIdx.x * SCAN_BLK + threadIdx.x;
    int v = 0;
    if (i < N_NODES) {
        v = g_degi[i];
        g_dinv[i] = rsqrtf((float)v + 1.0f);
    }
    sdata[threadIdx.x] = v;
    __syncthreads();
    for (int s = SCAN_BLK / 2; s > 0; s >>= 1) {
        if (threadIdx.x < s) sdata[threadIdx.x] += sdata[threadIdx.x + s];
        __syncthreads();
    }
    if (threadIdx.x == 0) g_bsum[blockIdx.x] = sdata[0];
}

// ---------------- scan phase 2: per-block scan + cross-block prefix -------
__global__ void scan_p3() {
    __shared__ int wsum[32];
    __shared__ int sprefix;
    int t = threadIdx.x;
    // warp 0 computes sum of preceding block totals (warp-parallel)
    if (t < 32) {
        int acc = 0;
        for (int j = t; j < NB; j += 32)
            if (j < blockIdx.x) acc += g_bsum[j];
#pragma unroll
        for (int off = 16; off > 0; off >>= 1)
            acc += __shfl_xor_sync(0xffffffffu, acc, off);
        if (t == 0) sprefix = acc;
    }
    int i = blockIdx.x * SCAN_BLK + t;
    int v = (i < N_NODES) ? g_degi[i] : 0;
    int lane = t & 31, w = t >> 5;
    int x = v;
#pragma unroll
    for (int off = 1; off < 32; off <<= 1) {
        int y = __shfl_up_sync(0xffffffffu, x, off);
        if (lane >= off) x += y;
    }
    if (lane == 31) wsum[w] = x;
    __syncthreads();
    if (w == 0) {
        int y = wsum[lane];
#pragma unroll
        for (int off = 1; off < 32; off <<= 1) {
            int z = __shfl_up_sync(0xffffffffu, y, off);
            if (lane >= off) y += z;
        }
        wsum[lane] = y;
    }
    __syncthreads();
    int incl = x + ((w > 0) ? wsum[w - 1] : 0) + sprefix;
    if (i < N_NODES) {
        g_off[i] = incl - v;
        g_cur[i] = incl - v;
        if (i == N_NODES - 1) g_off[N_NODES] = incl;
    }
}

// ---------------- CSR build (counting-sort scatter, packed payload) -------
__global__ void build_csr(const void* __restrict__ edges) {
    int e = blockIdx.x * blockDim.x + threadIdx.x;
    if (e >= N_EDGES) return;
    int s = edge_at(edges, e);
    int d = edge_at(edges, (long long)N_EDGES + e);
    int pos = atomicAdd(&g_cur[d], 1);
    g_edge[pos] = make_int2(s, __float_as_int(g_dinv[s]));
}

// ---------------- GEMM1: h1 = X @ W1 (64 nodes/block, 4x4 blocked) --------
__global__ __launch_bounds__(256) void gemm1_kernel(const float* __restrict__ X,
                                                    const float* __restrict__ W1) {
    __shared__ float xs[64 * 65];
    __shared__ float ws[64 * 64];
    int tid = threadIdx.x;
    int base = blockIdx.x * 64;
    for (int i = tid; i < 64 * 64; i += 256) ws[i] = W1[i];
    for (int i = tid; i < 64 * 64; i += 256) {
        int n = i >> 6, k = i & 63;
        int node = base + n;
        xs[n * 65 + k] = (node < N_NODES) ? X[(size_t)node * 64 + k] : 0.0f;
    }
    __syncthreads();

    int node_t = tid >> 4;   // 0..15
    int col_t  = tid & 15;   // 0..15
    float acc[4][4] = {};
#pragma unroll
    for (int k = 0; k < 64; k++) {
        float xv[4], wv[4];
#pragma unroll
        for (int i = 0; i < 4; i++) xv[i] = xs[(node_t * 4 + i) * 65 + k];
#pragma unroll
        for (int j = 0; j < 4; j++) wv[j] = ws[k * 64 + col_t + 16 * j];
#pragma unroll
        for (int i = 0; i < 4; i++)
#pragma unroll
            for (int j = 0; j < 4; j++) acc[i][j] = fmaf(xv[i], wv[j], acc[i][j]);
    }
#pragma unroll
    for (int i = 0; i < 4; i++) {
        int node = base + node_t * 4 + i;
        if (node < N_NODES) {
#pragma unroll
            for (int j = 0; j < 4; j++)
                g_h1[(size_t)node * 64 + col_t + 16 * j] = acc[i][j];
        }
    }
}

// ---------------- agg1: x1 = relu(A_hat h1 + b1) (warp/node, float2) ------
__global__ __launch_bounds__(256) void agg1_kernel(const float* __restrict__ b1) {
    int node = blockIdx.x * 8 + threadIdx.y;
    if (node >= N_NODES) return;
    int lane = threadIdx.x;   // 0..31, handles cols 2*lane, 2*lane+1
    const float2* h1 = (const float2*)g_h1;
    float di = g_dinv[node];
    float2 acc = h1[(size_t)node * 32 + lane];
    acc.x *= di; acc.y *= di;                 // self loop (final *di later)
    int beg = g_off[node], end = g_off[node + 1];
    int i = beg;
    for (; i + 4 <= end; i += 4) {
        int2 e0 = g_edge[i], e1 = g_edge[i + 1], e2 = g_edge[i + 2], e3 = g_edge[i + 3];
        float2 v0 = __ldg(&h1[(size_t)e0.x * 32 + lane]);
        float2 v1 = __ldg(&h1[(size_t)e1.x * 32 + lane]);
        float2 v2 = __ldg(&h1[(size_t)e2.x * 32 + lane]);
        float2 v3 = __ldg(&h1[(size_t)e3.x * 32 + lane]);
        float w0 = __int_as_float(e0.y), w1 = __int_as_float(e1.y);
        float w2 = __int_as_float(e2.y), w3 = __int_as_float(e3.y);
        acc.x = fmaf(v0.x, w0, acc.x); acc.y = fmaf(v0.y, w0, acc.y);
        acc.x = fmaf(v1.x, w1, acc.x); acc.y = fmaf(v1.y, w1, acc.y);
        acc.x = fmaf(v2.x, w2, acc.x); acc.y = fmaf(v2.y, w2, acc.y);
        acc.x = fmaf(v3.x, w3, acc.x); acc.y = fmaf(v3.y, w3, acc.y);
    }
    for (; i < end; i++) {
        int2 e = g_edge[i];
        float2 v = __ldg(&h1[(size_t)e.x * 32 + lane]);
        float w = __int_as_float(e.y);
        acc.x = fmaf(v.x, w, acc.x); acc.y = fmaf(v.y, w, acc.y);
    }
    float rx = fmaf(acc.x, di, b1[2 * lane]);
    float ry = fmaf(acc.y, di, b1[2 * lane + 1]);
    ((float2*)g_x1)[(size_t)node * 32 + lane] =
        make_float2(fmaxf(rx, 0.0f), fmaxf(ry, 0.0f));
}

// ---------------- GEMM2: h2 = x1 @ W2 (128 nodes/block, 2x4 blocked) ------
__global__ __launch_bounds__(256) void gemm2_kernel(const float* __restrict__ W2) {
    __shared__ float xs[128 * 65];
    __shared__ float ws[64 * 16];
    int tid = threadIdx.x;
    int base = blockIdx.x * 128;
    for (int i = tid; i < 64 * 16; i += 256) ws[i] = W2[i];
    for (int i = tid; i < 128 * 64; i += 256) {
        int n = i >> 6, k = i & 63;
        int node = base + n;
        xs[n * 65 + k] = (node < N_NODES) ? g_x1[(size_t)node * 64 + k] : 0.0f;
    }
    __syncthreads();

    int node_t = tid >> 2;   // 0..63
    int col_t  = tid & 3;    // 0..3
    float acc[2][4] = {};
#pragma unroll
    for (int k = 0; k < 64; k++) {
        float xv[2], wv[4];
#pragma unroll
        for (int i = 0; i < 2; i++) xv[i] = xs[(node_t * 2 + i) * 65 + k];
#pragma unroll
        for (int j = 0; j < 4; j++) wv[j] = ws[k * 16 + col_t + 4 * j];
#pragma unroll
        for (int i = 0; i < 2; i++)
#pragma unroll
            for (int j = 0; j < 4; j++) acc[i][j] = fmaf(xv[i], wv[j], acc[i][j]);
    }
#pragma unroll
    for (int i = 0; i < 2; i++) {
        int node = base + node_t * 2 + i;
        if (node < N_NODES) {
#pragma unroll
            for (int j = 0; j < 4; j++)
                g_h2[(size_t)node * 16 + col_t + 4 * j] = acc[i][j];
        }
    }
}

// ---------------- agg2: out = A_hat h2 + b2 (warp/node, split halves) -----
__global__ __launch_bounds__(256) void agg2_kernel(const float* __restrict__ b2,
                                                   float* __restrict__ dout) {
    int node = blockIdx.x * 8 + threadIdx.y;
    if (node >= N_NODES) return;
    int lane = threadIdx.x;
    int c = lane & 15;
    int half = lane >> 4;
    float di = g_dinv[node];
    float acc = (half == 0) ? g_h2[(size_t)node * 16 + c] * di : 0.0f;
    int beg = g_off[node], end = g_off[node + 1];
    int i = beg + half;
    // process pairs (i, i+2); both must be in range: i+2 < end
    for (; i + 2 < end; i += 4) {
        int2 e0 = g_edge[i], e1 = g_edge[i + 2];
        float v0 = __ldg(&g_h2[(size_t)e0.x * 16 + c]);
        float v1 = __ldg(&g_h2[(size_t)e1.x * 16 + c]);
        acc = fmaf(v0, __int_as_float(e0.y), acc);
        acc = fmaf(v1, __int_as_float(e1.y), acc);
    }
    if (i < end) {
        int2 e = g_edge[i];
        acc = fmaf(__ldg(&g_h2[(size_t)e.x * 16 + c]), __int_as_float(e.y), acc);
    }
    acc += __shfl_xor_sync(0xffffffffu, acc, 16);
    if (half == 0)
        dout[(size_t)node * 16 + c] = fmaf(acc, di, b2[c]);
}

// ---------------- launch --------------------------------------------------
extern "C" void kernel_launch(void* const* d_in, const int* in_sizes, int n_in,
                              void* d_out, int out_size) {
    const float* X  = (const float*)d_in[0];
    const void*  EI = (const void*)d_in[1];
    const float* W1 = (const float*)d_in[2];
    const float* b1 = (const float*)d_in[3];
    const float* W2 = (const float*)d_in[4];
    const float* b2 = (const float*)d_in[5];
    float* dout = (float*)d_out;
    (void)in_sizes; (void)n_in; (void)out_size;

    const int T = 256;

    pre_kernel<<<(N_NODES + T - 1) / T, T>>>((const int*)EI);
    degree_kernel<<<(N_EDGES + T - 1) / T, T>>>(EI);
    scan_p1<<<NB, SCAN_BLK>>>();
    scan_p3<<<NB, SCAN_BLK>>>();
    build_csr<<<(N_EDGES + T - 1) / T, T>>>(EI);

    gemm1_kernel<<<(N_NODES + 63) / 64, 256>>>(X, W1);
    agg1_kernel<<<(N_NODES + 7) / 8, dim3(32, 8)>>>(b1);
    gemm2_kernel<<<(N_NODES + 127) / 128, 256>>>(W2);
    agg2_kernel<<<(N_NODES + 7) / 8, dim3(32, 8)>>>(b2, dout);
}

// round 5
// speedup vs baseline: 1.8689x; 1.0534x over previous
#include <cuda_runtime.h>
#include <cuda_bf16.h>

#define N_NODES 100000
#define N_EDGES 1000000
#define DF 64
#define NC 16
#define PRE_BLOCKS 98
#define PRE_THREADS 1024
#define PRE_TOTAL (PRE_BLOCKS * PRE_THREADS)   // 100352 >= N_NODES

// ---------------- device scratch (no allocations allowed) ----------------
__device__ int      g_degi[N_NODES];
__device__ float    g_dinv[N_NODES];
__device__ int      g_off[N_NODES + 1];
__device__ int      g_cur[N_NODES];
__device__ int      g_bsum[PRE_BLOCKS];
__device__ int2     g_edge[N_EDGES];             // packed (src, bits(dinv[src]))
__device__ float    g_h1[(size_t)N_NODES * DF];  // X @ W1
__device__ float    g_h2[(size_t)N_NODES * NC];  // relu(agg1) @ W2
__device__ int      g_idx64;
__device__ unsigned g_barcnt[4];                 // cumulative grid-barrier tickets

// ---------------- cumulative grid barrier (graph-replay safe) -------------
__device__ __forceinline__ void grid_barrier(int i) {
    __syncthreads();
    if (threadIdx.x == 0) {
        __threadfence();
        unsigned tkt = atomicAdd(&g_barcnt[i], 1u) + 1u;
        unsigned target = ((tkt + (PRE_BLOCKS - 1u)) / PRE_BLOCKS) * PRE_BLOCKS;
        volatile unsigned* p = &g_barcnt[i];
        while (*p < target) { }
        __threadfence();
    }
    __syncthreads();
}

// ---------------- fused preprocessing ------------------------------------
__global__ __launch_bounds__(PRE_THREADS)
void prep_kernel(const void* __restrict__ edges) {
    int tid = blockIdx.x * PRE_THREADS + threadIdx.x;

    // Phase A: zero degrees + detect index width (block 0)
    if (tid < N_NODES) g_degi[tid] = 0;
    if (blockIdx.x == 0) {
        __shared__ int any_nz;
        if (threadIdx.x == 0) any_nz = 0;
        __syncthreads();
        const int* e32 = (const int*)edges;
        for (int j = threadIdx.x; j < 4096; j += PRE_THREADS)
            if (e32[2 * j + 1] != 0) any_nz = 1;
        __syncthreads();
        if (threadIdx.x == 0) g_idx64 = (any_nz == 0) ? 1 : 0;
    }
    grid_barrier(0);

    int idx64 = g_idx64;
    const long long* e64 = (const long long*)edges;
    const int*       e32 = (const int*)edges;

    // Phase B: in-degree histogram
    for (int e = tid; e < N_EDGES; e += PRE_TOTAL) {
        int d = idx64 ? (int)e64[(long long)N_EDGES + e] : e32[N_EDGES + e];
        atomicAdd(&g_degi[d], 1);
    }
    grid_barrier(1);

    // Phase C: dinv + block-local inclusive scan
    int v = (tid < N_NODES) ? g_degi[tid] : 0;
    if (tid < N_NODES) g_dinv[tid] = rsqrtf((float)v + 1.0f);
    __shared__ int wsum[32];
    int lane = threadIdx.x & 31, w = threadIdx.x >> 5;
    int x = v;
#pragma unroll
    for (int off = 1; off < 32; off <<= 1) {
        int y = __shfl_up_sync(0xffffffffu, x, off);
        if (lane >= off) x += y;
    }
    if (lane == 31) wsum[w] = x;
    __syncthreads();
    if (w == 0) {
        int y = wsum[lane];
#pragma unroll
        for (int off = 1; off < 32; off <<= 1) {
            int z = __shfl_up_sync(0xffffffffu, y, off);
            if (lane >= off) y += z;
        }
        wsum[lane] = y;
    }
    __syncthreads();
    int incl_local = x + ((w > 0) ? wsum[w - 1] : 0);
    if (threadIdx.x == PRE_THREADS - 1) g_bsum[blockIdx.x] = incl_local;
    grid_barrier(2);

    // Phase D: cross-block prefix + write offsets/cursors
    __shared__ int sprefix_s;
    if (threadIdx.x < 32) {
        int acc = 0;
        for (int j = threadIdx.x; j < blockIdx.x; j += 32) acc += g_bsum[j];
#pragma unroll
        for (int off = 16; off > 0; off >>= 1)
            acc += __shfl_xor_sync(0xffffffffu, acc, off);
        if (threadIdx.x == 0) sprefix_s = acc;
    }
    __syncthreads();
    int incl = incl_local + sprefix_s;
    if (tid < N_NODES) {
        g_off[tid] = incl - v;
        g_cur[tid] = incl - v;
        if (tid == N_NODES - 1) g_off[N_NODES] = incl;
    }
    grid_barrier(3);

    // Phase E: counting-sort scatter into CSR (packed payload)
    for (int e = tid; e < N_EDGES; e += PRE_TOTAL) {
        int s, d;
        if (idx64) {
            s = (int)e64[e];
            d = (int)e64[(long long)N_EDGES + e];
        } else {
            s = e32[e];
            d = e32[N_EDGES + e];
        }
        int pos = atomicAdd(&g_cur[d], 1);
        g_edge[pos] = make_int2(s, __float_as_int(g_dinv[s]));
    }
}

// ---------------- GEMM1: h1 = X @ W1 (64 nodes/block, 4x4 blocked) --------
__global__ __launch_bounds__(256) void gemm1_kernel(const float* __restrict__ X,
                                                    const float* __restrict__ W1) {
    __shared__ float xs[64 * 65];
    __shared__ float ws[64 * 64];
    int tid = threadIdx.x;
    int base = blockIdx.x * 64;
    for (int i = tid; i < 64 * 64; i += 256) ws[i] = W1[i];
    for (int i = tid; i < 64 * 64; i += 256) {
        int n = i >> 6, k = i & 63;
        int node = base + n;
        xs[n * 65 + k] = (node < N_NODES) ? X[(size_t)node * 64 + k] : 0.0f;
    }
    __syncthreads();

    int node_t = tid >> 4;   // 0..15
    int col_t  = tid & 15;   // 0..15
    float acc[4][4] = {};
#pragma unroll
    for (int k = 0; k < 64; k++) {
        float xv[4], wv[4];
#pragma unroll
        for (int i = 0; i < 4; i++) xv[i] = xs[(node_t * 4 + i) * 65 + k];
#pragma unroll
        for (int j = 0; j < 4; j++) wv[j] = ws[k * 64 + col_t + 16 * j];
#pragma unroll
        for (int i = 0; i < 4; i++)
#pragma unroll
            for (int j = 0; j < 4; j++) acc[i][j] = fmaf(xv[i], wv[j], acc[i][j]);
    }
#pragma unroll
    for (int i = 0; i < 4; i++) {
        int node = base + node_t * 4 + i;
        if (node < N_NODES) {
#pragma unroll
            for (int j = 0; j < 4; j++)
                g_h1[(size_t)node * 64 + col_t + 16 * j] = acc[i][j];
        }
    }
}

// ------- agg1 + gemm2 fused: h2 = relu(A_hat h1 + b1) @ W2 ----------------
__global__ __launch_bounds__(256) void agg1_gemm2_kernel(const float* __restrict__ b1,
                                                         const float* __restrict__ W2) {
    __shared__ float w2s[64][17];    // [k][c], padded
    __shared__ float x1s[8][64];     // per-warp x1 row
    int tid = threadIdx.x;
    for (int i = tid; i < 64 * 16; i += 256) w2s[i >> 4][i & 15] = W2[i];
    __syncthreads();

    int wy = tid >> 5;               // warp id 0..7
    int lane = tid & 31;
    int node = blockIdx.x * 8 + wy;
    if (node >= N_NODES) return;

    const float2* h1 = (const float2*)g_h1;
    float di = g_dinv[node];
    float2 acc = h1[(size_t)node * 32 + lane];
    acc.x *= di; acc.y *= di;        // self loop (final *di below)
    int beg = g_off[node], end = g_off[node + 1];
    int i = beg;
    for (; i + 4 <= end; i += 4) {
        int2 e0 = g_edge[i], e1 = g_edge[i + 1], e2 = g_edge[i + 2], e3 = g_edge[i + 3];
        float2 v0 = __ldg(&h1[(size_t)e0.x * 32 + lane]);
        float2 v1 = __ldg(&h1[(size_t)e1.x * 32 + lane]);
        float2 v2 = __ldg(&h1[(size_t)e2.x * 32 + lane]);
        float2 v3 = __ldg(&h1[(size_t)e3.x * 32 + lane]);
        float w0 = __int_as_float(e0.y), w1 = __int_as_float(e1.y);
        float w2 = __int_as_float(e2.y), w3 = __int_as_float(e3.y);
        acc.x = fmaf(v0.x, w0, acc.x); acc.y = fmaf(v0.y, w0, acc.y);
        acc.x = fmaf(v1.x, w1, acc.x); acc.y = fmaf(v1.y, w1, acc.y);
        acc.x = fmaf(v2.x, w2, acc.x); acc.y = fmaf(v2.y, w2, acc.y);
        acc.x = fmaf(v3.x, w3, acc.x); acc.y = fmaf(v3.y, w3, acc.y);
    }
    for (; i < end; i++) {
        int2 e = g_edge[i];
        float2 v = __ldg(&h1[(size_t)e.x * 32 + lane]);
        float w = __int_as_float(e.y);
        acc.x = fmaf(v.x, w, acc.x); acc.y = fmaf(v.y, w, acc.y);
    }
    float rx = fmaxf(fmaf(acc.x, di, b1[2 * lane]), 0.0f);
    float ry = fmaxf(fmaf(acc.y, di, b1[2 * lane + 1]), 0.0f);
    x1s[wy][2 * lane]     = rx;
    x1s[wy][2 * lane + 1] = ry;
    __syncwarp();

    // in-warp gemm2: h2[c] = sum_k x1[k] * W2[k][c]
    int c = lane & 15, h = lane >> 4;
    float s = 0.0f;
#pragma unroll
    for (int kk = 0; kk < 32; kk++) {
        int k = h * 32 + kk;
        s = fmaf(x1s[wy][k], w2s[k][c], s);
    }
    s += __shfl_xor_sync(0xffffffffu, s, 16);
    if (h == 0) g_h2[(size_t)node * 16 + c] = s;
}

// ---------------- agg2: out = A_hat h2 + b2 (warp/node, split halves) -----
__global__ __launch_bounds__(256) void agg2_kernel(const float* __restrict__ b2,
                                                   float* __restrict__ dout) {
    int node = blockIdx.x * 8 + threadIdx.y;
    if (node >= N_NODES) return;
    int lane = threadIdx.x;
    int c = lane & 15;
    int half = lane >> 4;
    float di = g_dinv[node];
    float acc = (half == 0) ? g_h2[(size_t)node * 16 + c] * di : 0.0f;
    int beg = g_off[node], end = g_off[node + 1];
    int i = beg + half;
    for (; i + 2 < end; i += 4) {
        int2 e0 = g_edge[i], e1 = g_edge[i + 2];
        float v0 = __ldg(&g_h2[(size_t)e0.x * 16 + c]);
        float v1 = __ldg(&g_h2[(size_t)e1.x * 16 + c]);
        acc = fmaf(v0, __int_as_float(e0.y), acc);
        acc = fmaf(v1, __int_as_float(e1.y), acc);
    }
    if (i < end) {
        int2 e = g_edge[i];
        acc = fmaf(__ldg(&g_h2[(size_t)e.x * 16 + c]), __int_as_float(e.y), acc);
    }
    acc += __shfl_xor_sync(0xffffffffu, acc, 16);
    if (half == 0)
        dout[(size_t)node * 16 + c] = fmaf(acc, di, b2[c]);
}

// ---------------- launch --------------------------------------------------
extern "C" void kernel_launch(void* const* d_in, const int* in_sizes, int n_in,
                              void* d_out, int out_size) {
    const float* X  = (const float*)d_in[0];
    const void*  EI = (const void*)d_in[1];
    const float* W1 = (const float*)d_in[2];
    const float* b1 = (const float*)d_in[3];
    const float* W2 = (const float*)d_in[4];
    const float* b2 = (const float*)d_in[5];
    float* dout = (float*)d_out;
    (void)in_sizes; (void)n_in; (void)out_size;

    prep_kernel<<<PRE_BLOCKS, PRE_THREADS>>>(EI);
    gemm1_kernel<<<(N_NODES + 63) / 64, 256>>>(X, W1);
    agg1_gemm2_kernel<<<(N_NODES + 7) / 8, 256>>>(b1, W2);
    agg2_kernel<<<(N_NODES + 7) / 8, dim3(32, 8)>>>(b2, dout);
}